// round 13
// baseline (speedup 1.0000x reference)
#include <cuda_runtime.h>
#include <cuda_fp16.h>
#include <cstdint>

// out = relu( (S0@(x*sd0) + S1@(x*sd1) + S2@(x*sd2)) @ W )
// Big GEMM: M=8192, N=128, K=3*8192, fp16 operands, fp32 accum.
// R5 skeleton (BM=64, BK=64, 8 warps 2m x 4n, 2 CTAs/SM) + ldmatrix A frags
// + kk-level fragment double buffering + 3-stage A ring.
// 896 CTAs = 128 row-blocks x 7 k-slices.

#define GN 8192
#define GD 128
#define BM 64
#define BK 64
#define NSTB 4
#define NSTA 3
#define AWRD 36                      // A words (f16x2) per row: 32 + 4 pad
#define A_STG_W (BM * AWRD)          // 2304 words per A stage
#define B_STG_W (32 * 128)           // 4096 words per B stage (kpair x chan)
#define SMEM_MAIN ((NSTB * B_STG_W + NSTA * A_STG_W) * 4)  // 93,184 B
#define NSLICE 7
#define KT_TOT 384                   // 3*8192/64

// Scratch (no allocation allowed)
__device__ __align__(16) __half g_Xt[3ull * GN * GD];        // 6 MB, tile-blocked
__device__ float g_P[(size_t)NSLICE * GN * GD];              // partials

__device__ __forceinline__ void cp_async16(void* smem_dst, const void* gsrc) {
    uint32_t s = (uint32_t)__cvta_generic_to_shared(smem_dst);
    asm volatile("cp.async.cg.shared.global [%0], [%1], 16;\n" ::"r"(s), "l"(gsrc));
}
__device__ __forceinline__ void cp_commit() {
    asm volatile("cp.async.commit_group;\n" ::);
}
template <int N>
__device__ __forceinline__ void cp_wait() {
    asm volatile("cp.async.wait_group %0;\n" ::"n"(N));
}

__device__ __forceinline__ void mma_f16(float d[4], const uint32_t a[4],
                                        const uint32_t b[2]) {
    asm volatile(
        "mma.sync.aligned.m16n8k16.row.col.f32.f16.f16.f32 "
        "{%0,%1,%2,%3}, {%4,%5,%6,%7}, {%8,%9}, {%0,%1,%2,%3};\n"
        : "+f"(d[0]), "+f"(d[1]), "+f"(d[2]), "+f"(d[3])
        : "r"(a[0]), "r"(a[1]), "r"(a[2]), "r"(a[3]), "r"(b[0]), "r"(b[1]));
}

__device__ __forceinline__ void ldmatrix_x4(uint32_t& r0, uint32_t& r1,
                                            uint32_t& r2, uint32_t& r3,
                                            uint32_t saddr) {
    asm volatile(
        "ldmatrix.sync.aligned.m8n8.x4.shared.b16 {%0,%1,%2,%3}, [%4];"
        : "=r"(r0), "=r"(r1), "=r"(r2), "=r"(r3)
        : "r"(saddr));
}

__device__ __forceinline__ uint32_t pack_h2(float a, float b) {
    __half2 h = __floats2half2_rn(a, b);
    return *reinterpret_cast<uint32_t*>(&h);
}

// Kernel 1: pack B = fp16(x[k][c] * sd_s[c]) into tile-blocked XOR layout.
// Tile g (= s*128 + kt): 4096 f16x2 words,
//   word[kp*128 + (c ^ ((kp&3)<<3))] = { x[kt*64+2kp][c]*sd, x[kt*64+2kp+1][c]*sd }
__global__ __launch_bounds__(256) void prep_xt(const float* __restrict__ x,
                                               const float* __restrict__ sd0,
                                               const float* __restrict__ sd1,
                                               const float* __restrict__ sd2) {
    __shared__ float xs[64 * 128];
    __shared__ float sds[3][128];
    const int tid = threadIdx.x;
    const int kb = blockIdx.x * 64;

#pragma unroll
    for (int j = 0; j < 8; j++) {
        int idx = j * 256 + tid;
        ((float4*)xs)[idx] = ((const float4*)(x + (size_t)kb * GD))[idx];
    }
    if (tid < 128) {
        sds[0][tid] = sd0[tid];
        sds[1][tid] = sd1[tid];
        sds[2][tid] = sd2[tid];
    }
    __syncthreads();

    __half2* dst = (__half2*)g_Xt;
#pragma unroll
    for (int s = 0; s < 3; s++) {
        __half2* blk = dst + ((size_t)(s * 128 + blockIdx.x)) * 4096;
#pragma unroll
        for (int w16 = 0; w16 < 16; w16++) {
            int w = w16 * 256 + tid;
            int kp = w >> 7;
            int c = (w & 127) ^ ((kp & 3) << 3);
            float sc = sds[s][c];
            blk[w] = __floats2half2_rn(xs[(2 * kp) * 128 + c] * sc,
                                       xs[(2 * kp + 1) * 128 + c] * sc);
        }
    }
}

// Kernel 2: main GEMM. grid 896 = 128 row-blocks x 7 slices, 2 CTAs/SM.
// 8 warps in 2(m) x 4(n); warp tile 32x32; mma.m16n8k16 fp16 -> fp32.
// A: LDG fp32 -> f16x2 regs -> STS (3-stage ring). B: cp.async (4-stage).
// compute: kk-level fragment double buffering, A via ldmatrix.x4.
__global__ __launch_bounds__(256, 2) void main_gemm(const float* __restrict__ S0,
                                                    const float* __restrict__ S1,
                                                    const float* __restrict__ S2) {
    extern __shared__ uint32_t smw[];
    uint32_t* Bs = smw;                      // NSTB * B_STG_W
    uint32_t* As = smw + NSTB * B_STG_W;     // NSTA * A_STG_W

    const int tid = threadIdx.x;
    const int slice = blockIdx.x % NSLICE;
    const int row_blk = blockIdx.x / NSLICE;
    const int block_row = row_blk * BM;
    const int kt_begin = (slice * KT_TOT) / NSLICE;
    const int KT = ((slice + 1) * KT_TOT) / NSLICE - kt_begin;

    const int wid = tid >> 5, lane = tid & 31;
    const int warp_m = wid & 1, warp_n = wid >> 1;
    const int gid = lane >> 2, tig = lane & 3;
    const int m_base = warp_m * 32, n_base = warp_n * 32;

    // ldmatrix .x4 source rows: lanes 0-7 -> rows m_base+0..7 (kp+0..3),
    // 8-15 -> m_base+8..15 (kp+0..3), 16-23 -> m_base+0..7 (kp+4..7),
    // 24-31 -> m_base+8..15 (kp+4..7). Fragment regs then match the scalar
    // mapping aw[r*AWRD + kp0 + tig] used by the verified R5 kernel.
    const int lmat_row = m_base + (lane & 15);
    const int lmat_kp = (lane >> 4) * 4;
    const uint32_t As_s = (uint32_t)__cvta_generic_to_shared(As);

    float acc[2][4][4];
#pragma unroll
    for (int mi = 0; mi < 2; mi++)
#pragma unroll
        for (int ni = 0; ni < 4; ni++)
#pragma unroll
            for (int q = 0; q < 4; q++) acc[mi][ni][q] = 0.f;

    uint32_t regA[8];

    auto srcS = [&](int g) -> const float* {
        int s = g >> 7;
        const float* p = (s == 0) ? S0 : (s == 1) ? S1 : S2;
        return p + (size_t)block_row * GN + ((g & 127) << 6);
    };

    auto issueB = [&](int stage, int kt) {
        const char* src =
            (const char*)g_Xt + (size_t)(kt_begin + kt) * (64 * GD * 2);
        char* dst = (char*)(Bs + stage * B_STG_W);
#pragma unroll
        for (int j = 0; j < 4; j++) {
            int idx = j * 256 + tid;
            cp_async16(dst + idx * 16, src + idx * 16);
        }
    };

    // 64 rows x 16 float4 = 1024 float4; 4/thread -> 8 packed u32
    auto ldgA = [&](int kt) {
        const float* Ag = srcS(kt_begin + kt);
#pragma unroll
        for (int j = 0; j < 4; j++) {
            int idx = j * 256 + tid;
            int r = idx >> 4;
            int c4 = (idx & 15) * 4;
            float4 v = *(const float4*)(Ag + (size_t)r * GN + c4);
            regA[j * 2 + 0] = pack_h2(v.x, v.y);
            regA[j * 2 + 1] = pack_h2(v.z, v.w);
        }
    };

    auto stsA = [&](int buf) {
        uint32_t* aw = As + buf * A_STG_W;
#pragma unroll
        for (int j = 0; j < 4; j++) {
            int idx = j * 256 + tid;
            int r = idx >> 4;
            int q = (idx & 15) * 2;
            uint2 w;
            w.x = regA[j * 2 + 0];
            w.y = regA[j * 2 + 1];
            *(uint2*)&aw[r * AWRD + q] = w;
        }
    };

    auto loadFragA = [&](int astg, int kp0, uint32_t a[2][4]) {
#pragma unroll
        for (int mi = 0; mi < 2; mi++) {
            uint32_t addr =
                As_s +
                (astg * A_STG_W + (lmat_row + mi * 16) * AWRD + kp0 + lmat_kp) * 4;
            ldmatrix_x4(a[mi][0], a[mi][1], a[mi][2], a[mi][3], addr);
        }
    };
    auto loadFragB = [&](const uint32_t* bw, int kp0, uint32_t b[4][2]) {
#pragma unroll
        for (int ni = 0; ni < 4; ni++) {
            int cx = (n_base + ni * 8 + gid) ^ (tig << 3);
            b[ni][0] = bw[(kp0 + tig) * 128 + cx];
            b[ni][1] = bw[(kp0 + tig + 4) * 128 + cx];
        }
    };

    auto compute = [&](int kt, int astg) {
        const uint32_t* bw = Bs + (kt & 3) * B_STG_W;
        uint32_t afr[2][2][4];
        uint32_t bfr[2][4][2];
        loadFragA(astg, 0, afr[0]);
        loadFragB(bw, 0, bfr[0]);
#pragma unroll
        for (int kk = 0; kk < 4; kk++) {
            const int cur = kk & 1, nxt = cur ^ 1;
            if (kk < 3) {
                loadFragA(astg, (kk + 1) * 8, afr[nxt]);
                loadFragB(bw, (kk + 1) * 8, bfr[nxt]);
            }
#pragma unroll
            for (int mi = 0; mi < 2; mi++)
#pragma unroll
                for (int ni = 0; ni < 4; ni++)
                    mma_f16(acc[mi][ni], afr[cur][mi], bfr[cur][ni]);
        }
    };

    // prologue: B tiles 0..2 (cp.async); A tiles 0,1 in smem, tile 2 in regs
    issueB(0, 0);
    cp_commit();
    issueB(1, 1);
    cp_commit();
    issueB(2, 2);
    cp_commit();
    ldgA(0);
    stsA(0);
    ldgA(1);
    stsA(1);
    ldgA(2);

    int astg = 0;  // A ring slot holding tile kt
    for (int kt = 0; kt < KT; kt++) {
        cp_wait<NSTB - 2>();
        __syncthreads();
        int a2 = astg + 2;
        if (a2 >= NSTA) a2 -= NSTA;
        if (kt + 2 < KT) stsA(a2);  // write A(kt+2) into freed ring slot
        if (kt + 3 < KT) {
            ldgA(kt + 3);
            issueB((kt + 3) & 3, kt + 3);
        }
        cp_commit();
        compute(kt, astg);
        if (++astg == NSTA) astg = 0;
    }

    // store partial sums (fp32)
    float* P = g_P + (size_t)slice * GN * GD;
#pragma unroll
    for (int mi = 0; mi < 2; mi++) {
#pragma unroll
        for (int ni = 0; ni < 4; ni++) {
            int r = block_row + m_base + mi * 16 + gid;
            int c = n_base + ni * 8 + tig * 2;
            *(float2*)&P[(size_t)r * GD + c] =
                make_float2(acc[mi][ni][0], acc[mi][ni][1]);
            *(float2*)&P[(size_t)(r + 8) * GD + c] =
                make_float2(acc[mi][ni][2], acc[mi][ni][3]);
        }
    }
}

// Kernel 3: out = relu( (sum_slices P) @ W ).  grid 256 (32 rows each).
#define SMEM_FIN ((128 * 132 + 32 * 128) * 4)  // 83,968 B
__global__ __launch_bounds__(256, 2) void proj_relu(const float* __restrict__ W,
                                                    float* __restrict__ out) {
    extern __shared__ float fs[];
    float* Ws = fs;               // [128][132]
    float* agg = fs + 128 * 132;  // [32][128]
    const int tid = threadIdx.x;
    const int row0 = blockIdx.x * 32;

#pragma unroll
    for (int j = 0; j < 16; j++) {
        int idx = j * 256 + tid;
        int r = idx >> 5;
        int c4 = (idx & 31) * 4;
        *(float4*)&Ws[r * 132 + c4] = *(const float4*)&W[r * GD + c4];
    }
#pragma unroll
    for (int j = 0; j < 4; j++) {
        int idx = j * 256 + tid;
        int r = idx >> 5;
        int c4 = (idx & 31) * 4;
        float4 s = make_float4(0.f, 0.f, 0.f, 0.f);
#pragma unroll
        for (int sl = 0; sl < NSLICE; sl++) {
            float4 v = *(const float4*)&g_P[((size_t)sl * GN + row0 + r) * GD + c4];
            s.x += v.x; s.y += v.y; s.z += v.z; s.w += v.w;
        }
        *(float4*)&agg[r * 128 + c4] = s;
    }
    __syncthreads();

    const int tx = tid & 15;
    const int ty = tid >> 4;
    float acc[2][8];
#pragma unroll
    for (int i = 0; i < 2; i++)
#pragma unroll
        for (int j = 0; j < 8; j++) acc[i][j] = 0.f;

#pragma unroll 4
    for (int c = 0; c < 128; c++) {
        float a0 = agg[(ty * 2) * 128 + c];
        float a1 = agg[(ty * 2 + 1) * 128 + c];
        float w[8];
        *(float4*)&w[0] = *(float4*)&Ws[c * 132 + tx * 8];
        *(float4*)&w[4] = *(float4*)&Ws[c * 132 + tx * 8 + 4];
#pragma unroll
        for (int j = 0; j < 8; j++) {
            acc[0][j] = fmaf(a0, w[j], acc[0][j]);
            acc[1][j] = fmaf(a1, w[j], acc[1][j]);
        }
    }

#pragma unroll
    for (int i = 0; i < 2; i++) {
        float* dst = &out[(size_t)(row0 + ty * 2 + i) * GD + tx * 8];
        float4 v0, v1;
        v0.x = fmaxf(acc[i][0], 0.f);
        v0.y = fmaxf(acc[i][1], 0.f);
        v0.z = fmaxf(acc[i][2], 0.f);
        v0.w = fmaxf(acc[i][3], 0.f);
        v1.x = fmaxf(acc[i][4], 0.f);
        v1.y = fmaxf(acc[i][5], 0.f);
        v1.z = fmaxf(acc[i][6], 0.f);
        v1.w = fmaxf(acc[i][7], 0.f);
        *(float4*)&dst[0] = v0;
        *(float4*)&dst[4] = v1;
    }
}

extern "C" void kernel_launch(void* const* d_in, const int* in_sizes, int n_in,
                              void* d_out, int out_size) {
    const float* x = (const float*)d_in[0];
    const float* S0 = (const float*)d_in[1];
    const float* S1 = (const float*)d_in[2];
    const float* S2 = (const float*)d_in[3];
    const float* W = (const float*)d_in[4];
    const float* sd0 = (const float*)d_in[5];
    const float* sd1 = (const float*)d_in[6];
    const float* sd2 = (const float*)d_in[7];
    float* out = (float*)d_out;

    cudaFuncSetAttribute(main_gemm, cudaFuncAttributeMaxDynamicSharedMemorySize,
                         SMEM_MAIN);
    cudaFuncSetAttribute(proj_relu, cudaFuncAttributeMaxDynamicSharedMemorySize,
                         SMEM_FIN);

    prep_xt<<<GN / 64, 256>>>(x, sd0, sd1, sd2);
    main_gemm<<<128 * NSLICE, 256, SMEM_MAIN>>>(S0, S1, S2);
    proj_relu<<<GN / 32, 256, SMEM_FIN>>>(W, out);
}